// round 4
// baseline (speedup 1.0000x reference)
#include <cuda_runtime.h>
#include <math.h>

#define BN 32
#define TN 4096
#define DN 256
#define UN 256
#define NJ 1024

// ---------------- static device scratch (no runtime allocation) -------------
__device__ float    g_Zx[(size_t)TN * BN * NJ];   // [t*32+b][j]  512MB
__device__ float    g_Wp[512 * NJ];               // packed W: row k (0..255 s-part, 256..511 x-part), col j=g*256+u
__device__ float    g_S[2][BN][UN];               // double-buffered recurrent state
__device__ unsigned g_cnt[8][32];                 // per-team arrival counters (padded to 128B)
__device__ unsigned g_ep[8][32];                  // per-team epoch

// ---------------- f32x2 packed FMA helpers ----------------------------------
__device__ __forceinline__ unsigned long long pk2(float v) {
    unsigned long long r; unsigned u = __float_as_uint(v);
    asm("mov.b64 %0, {%1, %1};" : "=l"(r) : "r"(u));
    return r;
}
__device__ __forceinline__ unsigned long long fma2(unsigned long long a,
                                                   unsigned long long b,
                                                   unsigned long long c) {
    unsigned long long d;
    asm("fma.rn.f32x2 %0, %1, %2, %3;" : "=l"(d) : "l"(a), "l"(b), "l"(c));
    return d;
}
__device__ __forceinline__ float2 upk2(unsigned long long v) {
    unsigned lo, hi;
    asm("mov.b64 {%0, %1}, %2;" : "=r"(lo), "=r"(hi) : "l"(v));
    return make_float2(__uint_as_float(lo), __uint_as_float(hi));
}
__device__ __forceinline__ unsigned ld_acq(const unsigned* p) {
    unsigned v;
    asm volatile("ld.acquire.gpu.global.u32 %0, [%1];" : "=r"(v) : "l"(p) : "memory");
    return v;
}
__device__ __forceinline__ void st_rel(unsigned* p, unsigned v) {
    asm volatile("st.release.gpu.global.u32 [%0], %1;" :: "l"(p), "r"(v) : "memory");
}
__device__ __forceinline__ unsigned atom_add_acqrel(unsigned* p, unsigned v) {
    unsigned old;
    asm volatile("atom.acq_rel.gpu.global.add.u32 %0, [%1], %2;"
                 : "=r"(old) : "l"(p), "r"(v) : "memory");
    return old;
}
__device__ __forceinline__ float sigm(float z) { return 1.0f / (1.0f + __expf(-z)); }

// ---------------- kernel 0: pack weights, init state, reset barriers --------
__global__ __launch_bounds__(256) void k_init(const float* __restrict__ Wf,
                                              const float* __restrict__ Wi,
                                              const float* __restrict__ Wc,
                                              const float* __restrict__ Wo,
                                              const float* __restrict__ h0) {
    int idx = blockIdx.x * blockDim.x + threadIdx.x;
    if (idx < 512 * 1024) {
        int k = idx >> 10, j = idx & 1023;
        int g = j >> 8,    u = j & 255;
        const float* W = (g == 0) ? Wf : (g == 1) ? Wi : (g == 2) ? Wc : Wo;
        g_Wp[idx] = W[k * 256 + u];
    }
    if (idx < BN * UN) g_S[0][idx >> 8][idx & 255] = h0[idx];
    if (idx < 8) { g_cnt[idx][0] = 0u; g_ep[idx][0] = 0u; }
}

// ---------------- kernel 1: input projection GEMM ---------------------------
// Zx[m][j] = sum_d x[b][t][d] * Wp[256+d][j],  m = t*32+b.  64x64 tile, 4x4/thread.
__global__ __launch_bounds__(256) void k_gemm(const float* __restrict__ x) {
    __shared__ __align__(16) float As[16][64];   // [k][m]
    __shared__ __align__(16) float Bs[16][64];   // [k][n]

    const int tid = threadIdx.x;
    const int n0  = blockIdx.x * 64;
    const int m0  = blockIdx.y * 64;
    const int tm  = tid >> 4, tn = tid & 15;

    const int ar  = tid >> 2, akq = tid & 3;     // A-load role
    const int bkr = tid >> 4, bnq = tid & 15;    // B-load role

    const int m_glob = m0 + ar;
    const int bb = m_glob & 31, tt = m_glob >> 5;
    const float* arow = x + ((size_t)bb * TN + tt) * DN;

    unsigned long long a00=0, a01=0, a10=0, a11=0, a20=0, a21=0, a30=0, a31=0;

    float4 av = *(const float4*)(arow + akq * 4);
    float4 bv = *(const float4*)(g_Wp + (size_t)(256 + bkr) * NJ + n0 + bnq * 4);

    for (int k0 = 0; k0 < 256; k0 += 16) {
        __syncthreads();
        As[akq * 4 + 0][ar] = av.x;
        As[akq * 4 + 1][ar] = av.y;
        As[akq * 4 + 2][ar] = av.z;
        As[akq * 4 + 3][ar] = av.w;
        *(float4*)&Bs[bkr][bnq * 4] = bv;
        __syncthreads();

        if (k0 + 16 < 256) {
            av = *(const float4*)(arow + k0 + 16 + akq * 4);
            bv = *(const float4*)(g_Wp + (size_t)(256 + k0 + 16 + bkr) * NJ + n0 + bnq * 4);
        }
        #pragma unroll
        for (int kk = 0; kk < 16; kk++) {
            float4 a = *(const float4*)&As[kk][tm * 4];
            ulonglong2 w = *(const ulonglong2*)&Bs[kk][tn * 4];
            unsigned long long p;
            p = pk2(a.x); a00 = fma2(p, w.x, a00); a01 = fma2(p, w.y, a01);
            p = pk2(a.y); a10 = fma2(p, w.x, a10); a11 = fma2(p, w.y, a11);
            p = pk2(a.z); a20 = fma2(p, w.x, a20); a21 = fma2(p, w.y, a21);
            p = pk2(a.w); a30 = fma2(p, w.x, a30); a31 = fma2(p, w.y, a31);
        }
    }
    float2 lo, hi;
    lo = upk2(a00); hi = upk2(a01);
    *(float4*)(g_Zx + (size_t)(m0 + tm*4 + 0) * NJ + n0 + tn*4) = make_float4(lo.x, lo.y, hi.x, hi.y);
    lo = upk2(a10); hi = upk2(a11);
    *(float4*)(g_Zx + (size_t)(m0 + tm*4 + 1) * NJ + n0 + tn*4) = make_float4(lo.x, lo.y, hi.x, hi.y);
    lo = upk2(a20); hi = upk2(a21);
    *(float4*)(g_Zx + (size_t)(m0 + tm*4 + 2) * NJ + n0 + tn*4) = make_float4(lo.x, lo.y, hi.x, hi.y);
    lo = upk2(a30); hi = upk2(a31);
    *(float4*)(g_Zx + (size_t)(m0 + tm*4 + 3) * NJ + n0 + tn*4) = make_float4(lo.x, lo.y, hi.x, hi.y);
}

// ---------------- kernel 2: persistent recurrence ---------------------------
// 128 CTAs = 8 teams x 16 CTAs. Team owns batches [team*4, team*4+4).
// CTA rank r owns u-range [r*16, r*16+16) -> 64 gate columns, weights in SMEM.
#define REC_SMEM_FLOATS (256*64 + 256*4 + 16*256 + 256)
#define REC_SMEM_BYTES  (REC_SMEM_FLOATS * 4)

__global__ __launch_bounds__(256, 1) void k_rec(float* __restrict__ out) {
    extern __shared__ __align__(16) float sm[];
    float* Wsm = sm;                 // [k][jj]   256*64
    float* Ssm = sm + 256 * 64;      // [k][b]    256*4
    float* Zsm = Ssm + 256 * 4;      // [kg][zi]  16*256
    float* Zf  = Zsm + 16 * 256;     // [zi]      256

    const int tid  = threadIdx.x;
    const int cid  = blockIdx.x;
    const int team = cid >> 4;
    const int r    = cid & 15;
    const int b0   = team * 4;
    const int u0   = r * 16;

    // weight slice resident for whole kernel: Wsm[k][jj], jj = g*16+uu
    for (int i = tid; i < 256 * 64; i += 256) {
        int k = i >> 6, jj = i & 63;
        Wsm[i] = g_Wp[(size_t)k * NJ + ((jj >> 4) << 8) + u0 + (jj & 15)];
    }

    const int kg = tid >> 4, jq = tid & 15;         // matmul role
    const int k_beg = kg * 16, jj0 = jq * 4;
    const int rb = tid >> 6, rjj = tid & 63;        // reduce role (zi == tid)
    const int jcol = ((rjj >> 4) << 8) + u0 + (rjj & 15);
    const int fb = tid >> 4, fu = tid & 15;         // finalize role (tid < 64)
    const size_t c_off = (size_t)BN * TN * UN;

    __syncthreads();

    for (int t = 0; t < TN; t++) {
        const int cur = t & 1, nxt = cur ^ 1;

        // state -> SMEM as [k][b]  (L1-bypass: written by peer SMs last step)
        #pragma unroll
        for (int i = 0; i < 4; i++)
            Ssm[tid * 4 + i] = __ldcg(&g_S[cur][b0 + i][tid]);

        // prefetch this step's input projection for the reduce phase
        float zx = g_Zx[((size_t)(t * 32 + b0 + rb)) * NJ + jcol];

        __syncthreads();

        // partial recurrent matmul: 4 batches x 4 cols over 16 k's
        unsigned long long a00=0,a01=0,a10=0,a11=0,a20=0,a21=0,a30=0,a31=0;
        #pragma unroll
        for (int k = 0; k < 16; k++) {
            const int kk = k_beg + k;
            float4 s4 = *(const float4*)(Ssm + kk * 4);
            ulonglong2 w = *(const ulonglong2*)(Wsm + kk * 64 + jj0);
            unsigned long long p;
            p = pk2(s4.x); a00 = fma2(p, w.x, a00); a01 = fma2(p, w.y, a01);
            p = pk2(s4.y); a10 = fma2(p, w.x, a10); a11 = fma2(p, w.y, a11);
            p = pk2(s4.z); a20 = fma2(p, w.x, a20); a21 = fma2(p, w.y, a21);
            p = pk2(s4.w); a30 = fma2(p, w.x, a30); a31 = fma2(p, w.y, a31);
        }
        float2 lo, hi;
        lo = upk2(a00); hi = upk2(a01);
        *(float4*)(Zsm + kg*256 + 0*64 + jj0) = make_float4(lo.x, lo.y, hi.x, hi.y);
        lo = upk2(a10); hi = upk2(a11);
        *(float4*)(Zsm + kg*256 + 1*64 + jj0) = make_float4(lo.x, lo.y, hi.x, hi.y);
        lo = upk2(a20); hi = upk2(a21);
        *(float4*)(Zsm + kg*256 + 2*64 + jj0) = make_float4(lo.x, lo.y, hi.x, hi.y);
        lo = upk2(a30); hi = upk2(a31);
        *(float4*)(Zsm + kg*256 + 3*64 + jj0) = make_float4(lo.x, lo.y, hi.x, hi.y);

        __syncthreads();

        // reduce 16 partials + input projection
        float z = zx;
        #pragma unroll
        for (int g = 0; g < 16; g++) z += Zsm[g * 256 + tid];
        Zf[tid] = z;

        __syncthreads();

        // gate math + outputs (64 threads: 4 batches x 16 u's)
        if (tid < 64) {
            float zfv = Zf[fb * 64 +  0 + fu];
            float ziv = Zf[fb * 64 + 16 + fu];
            float zgv = Zf[fb * 64 + 32 + fu];
            float zov = Zf[fb * 64 + 48 + fu];
            float s_old = Ssm[(u0 + fu) * 4 + fb];
            float fg = sigm(zfv), ig = sigm(ziv), gg = sigm(zgv);
            float c  = ig * gg + fg * s_old;
            float o  = tanhf(zov);
            float ct = tanhf(c);
            float h  = o * ct;
            size_t oidx = ((size_t)(b0 + fb) * TN + t) * UN + (u0 + fu);
            out[oidx]         = h;
            out[c_off + oidx] = ct;
            g_S[nxt][b0 + fb][u0 + fu] = ct;
            __threadfence();
        }
        __syncthreads();

        // team-local barrier
        if (tid == 0) {
            unsigned old = atom_add_acqrel(&g_cnt[team][0], 1u);
            const unsigned tgt = 16u * (unsigned)(t + 1);
            if (old == tgt - 1u) {
                st_rel(&g_ep[team][0], (unsigned)(t + 1));
            } else {
                while (ld_acq(&g_ep[team][0]) < (unsigned)(t + 1)) { }
            }
        }
        __syncthreads();
    }
}

// ---------------- launcher ---------------------------------------------------
extern "C" void kernel_launch(void* const* d_in, const int* in_sizes, int n_in,
                              void* d_out, int out_size) {
    const float* x  = (const float*)d_in[0];
    const float* h0 = (const float*)d_in[1];
    const float* Wf = (const float*)d_in[2];
    const float* Wi = (const float*)d_in[3];
    const float* Wc = (const float*)d_in[4];
    const float* Wo = (const float*)d_in[5];
    float* out = (float*)d_out;

    cudaFuncSetAttribute(k_rec, cudaFuncAttributeMaxDynamicSharedMemorySize,
                         REC_SMEM_BYTES);

    k_init<<<2048, 256>>>(Wf, Wi, Wc, Wo, h0);
    dim3 gg(NJ / 64, (TN * BN) / 64);   // (16, 2048)
    k_gemm<<<gg, 256>>>(x);
    k_rec<<<128, 256, REC_SMEM_BYTES>>>(out);
}

// round 5
// speedup vs baseline: 1.1787x; 1.1787x over previous
#include <cuda_runtime.h>
#include <math.h>

#define BN 32
#define TN 4096
#define DN 256
#define UN 256
#define NJ 1024

// ---------------- static device scratch (no runtime allocation) -------------
__device__ float    g_Zx[(size_t)TN * BN * NJ];   // [t*32+b][j]  512MB input projection
__device__ float    g_Wp[512 * NJ];               // packed W: rows 0..255 s-part, 256..511 x-part; col j=g*256+u
__device__ float    g_S[2][BN][UN];               // double-buffered recurrent state
__device__ unsigned g_flag[8][16][32];            // per-(team,cta) step flags, 128B padded

// ---------------- f32x2 packed FMA helpers ----------------------------------
__device__ __forceinline__ unsigned long long pk2(float v) {
    unsigned long long r; unsigned u = __float_as_uint(v);
    asm("mov.b64 %0, {%1, %1};" : "=l"(r) : "r"(u));
    return r;
}
__device__ __forceinline__ unsigned long long pack2(float lo, float hi) {
    unsigned long long r;
    asm("mov.b64 %0, {%1, %2};" : "=l"(r)
        : "r"(__float_as_uint(lo)), "r"(__float_as_uint(hi)));
    return r;
}
__device__ __forceinline__ unsigned long long fma2(unsigned long long a,
                                                   unsigned long long b,
                                                   unsigned long long c) {
    unsigned long long d;
    asm("fma.rn.f32x2 %0, %1, %2, %3;" : "=l"(d) : "l"(a), "l"(b), "l"(c));
    return d;
}
__device__ __forceinline__ float2 upk2(unsigned long long v) {
    unsigned lo, hi;
    asm("mov.b64 {%0, %1}, %2;" : "=r"(lo), "=r"(hi) : "l"(v));
    return make_float2(__uint_as_float(lo), __uint_as_float(hi));
}
__device__ __forceinline__ unsigned ld_acq(const unsigned* p) {
    unsigned v;
    asm volatile("ld.acquire.gpu.global.u32 %0, [%1];" : "=r"(v) : "l"(p) : "memory");
    return v;
}
__device__ __forceinline__ void st_rel(unsigned* p, unsigned v) {
    asm volatile("st.release.gpu.global.u32 [%0], %1;" :: "l"(p), "r"(v) : "memory");
}
__device__ __forceinline__ float sigm(float z) { return 1.0f / (1.0f + __expf(-z)); }

// ---------------- kernel 0: pack weights, init state, reset flags -----------
__global__ __launch_bounds__(256) void k_init(const float* __restrict__ Wf,
                                              const float* __restrict__ Wi,
                                              const float* __restrict__ Wc,
                                              const float* __restrict__ Wo,
                                              const float* __restrict__ h0) {
    int idx = blockIdx.x * blockDim.x + threadIdx.x;
    if (idx < 512 * 1024) {
        int k = idx >> 10, j = idx & 1023;
        int g = j >> 8,    u = j & 255;
        const float* W = (g == 0) ? Wf : (g == 1) ? Wi : (g == 2) ? Wc : Wo;
        g_Wp[idx] = W[k * 256 + u];
    }
    if (idx < BN * UN) g_S[0][idx >> 8][idx & 255] = h0[idx];
    if (idx < 128) g_flag[idx >> 4][idx & 15][0] = 0u;   // graph replays: must reset
}

// ---------------- kernel 1: input projection GEMM ---------------------------
// Zx[m][j] = sum_d x[b][t][d] * Wp[256+d][j],  m = t*32+b.  64x64 tile, 4x4/thread.
__global__ __launch_bounds__(256) void k_gemm(const float* __restrict__ x) {
    __shared__ __align__(16) float As[16][64];   // [k][m]
    __shared__ __align__(16) float Bs[16][64];   // [k][n]

    const int tid = threadIdx.x;
    const int n0  = blockIdx.x * 64;
    const int m0  = blockIdx.y * 64;
    const int tm  = tid >> 4, tn = tid & 15;

    const int ar  = tid >> 2, akq = tid & 3;     // A-load role
    const int bkr = tid >> 4, bnq = tid & 15;    // B-load role

    const int m_glob = m0 + ar;
    const int bb = m_glob & 31, tt = m_glob >> 5;
    const float* arow = x + ((size_t)bb * TN + tt) * DN;

    unsigned long long a00=0, a01=0, a10=0, a11=0, a20=0, a21=0, a30=0, a31=0;

    float4 av = *(const float4*)(arow + akq * 4);
    float4 bv = *(const float4*)(g_Wp + (size_t)(256 + bkr) * NJ + n0 + bnq * 4);

    for (int k0 = 0; k0 < 256; k0 += 16) {
        __syncthreads();
        As[akq * 4 + 0][ar] = av.x;
        As[akq * 4 + 1][ar] = av.y;
        As[akq * 4 + 2][ar] = av.z;
        As[akq * 4 + 3][ar] = av.w;
        *(float4*)&Bs[bkr][bnq * 4] = bv;
        __syncthreads();

        if (k0 + 16 < 256) {
            av = *(const float4*)(arow + k0 + 16 + akq * 4);
            bv = *(const float4*)(g_Wp + (size_t)(256 + k0 + 16 + bkr) * NJ + n0 + bnq * 4);
        }
        #pragma unroll
        for (int kk = 0; kk < 16; kk++) {
            float4 a = *(const float4*)&As[kk][tm * 4];
            ulonglong2 w = *(const ulonglong2*)&Bs[kk][tn * 4];
            unsigned long long p;
            p = pk2(a.x); a00 = fma2(p, w.x, a00); a01 = fma2(p, w.y, a01);
            p = pk2(a.y); a10 = fma2(p, w.x, a10); a11 = fma2(p, w.y, a11);
            p = pk2(a.z); a20 = fma2(p, w.x, a20); a21 = fma2(p, w.y, a21);
            p = pk2(a.w); a30 = fma2(p, w.x, a30); a31 = fma2(p, w.y, a31);
        }
    }
    float2 lo, hi;
    lo = upk2(a00); hi = upk2(a01);
    *(float4*)(g_Zx + (size_t)(m0 + tm*4 + 0) * NJ + n0 + tn*4) = make_float4(lo.x, lo.y, hi.x, hi.y);
    lo = upk2(a10); hi = upk2(a11);
    *(float4*)(g_Zx + (size_t)(m0 + tm*4 + 1) * NJ + n0 + tn*4) = make_float4(lo.x, lo.y, hi.x, hi.y);
    lo = upk2(a20); hi = upk2(a21);
    *(float4*)(g_Zx + (size_t)(m0 + tm*4 + 2) * NJ + n0 + tn*4) = make_float4(lo.x, lo.y, hi.x, hi.y);
    lo = upk2(a30); hi = upk2(a31);
    *(float4*)(g_Zx + (size_t)(m0 + tm*4 + 3) * NJ + n0 + tn*4) = make_float4(lo.x, lo.y, hi.x, hi.y);
}

// ---------------- kernel 2: persistent recurrence ---------------------------
// 128 CTAs = 8 teams x 16 CTAs. Team owns batches [team*4, team*4+4).
// CTA rank r owns u-range [r*16, r*16+16).
// Column remap within CTA: jj = uu*4 + gate  (gates adjacent -> warp shuffle).
// Weights live in REGISTERS (16k x 4 gates per thread) for all 4096 steps.
__global__ __launch_bounds__(256, 1) void k_rec(float* __restrict__ out) {
    __shared__ __align__(16) float Ssm[256 * 4];   // [k][b]
    __shared__ __align__(16) float Zsm[16 * 256];  // [kg][zi],  zi = b*64 + uu*4 + g

    const int tid  = threadIdx.x;
    const int cid  = blockIdx.x;
    const int team = cid >> 4;
    const int r    = cid & 15;
    const int b0   = team * 4;
    const int u0   = r * 16;

    // matmul role: thread = (kg, jq) -> k in [kg*16, kg*16+16), uu = jq, all 4 gates
    const int kg    = tid >> 4;
    const int jq    = tid & 15;
    const int k_beg = kg * 16;

    // reduce/gate role: zi == tid -> (b, uu, g)
    const int gg = tid & 3;
    const int uu = (tid >> 2) & 15;
    const int bb = tid >> 6;
    const int jcol = gg * 256 + u0 + uu;   // global gate column for this zi
    const size_t c_off = (size_t)BN * TN * UN;

    // ---- load weight tile into registers (once) ----
    unsigned long long w0[16], w1[16];   // w0: gates {0,1}, w1: gates {2,3}
    #pragma unroll
    for (int k = 0; k < 16; k++) {
        const float* wr = g_Wp + (size_t)(k_beg + k) * NJ + u0 + jq;
        w0[k] = pack2(wr[0],   wr[256]);
        w1[k] = pack2(wr[512], wr[768]);
    }

    for (int t = 0; t < TN; t++) {
        const int cur = t & 1, nxt = cur ^ 1;

        // state -> SMEM as [k][b] (L2 path; written by peer SMs last step)
        #pragma unroll
        for (int i = 0; i < 4; i++)
            Ssm[tid * 4 + i] = __ldcg(&g_S[cur][b0 + i][tid]);

        // prefetch this step's input projection (consumed after the matmul)
        float zx = __ldcg(&g_Zx[((size_t)(t * 32 + b0 + bb)) * NJ + jcol]);

        __syncthreads();

        // recurrent matmul partials: 4 batches x 4 gate-cols over 16 k's, all-register weights
        unsigned long long a0x=0, a0y=0, a1x=0, a1y=0, a2x=0, a2y=0, a3x=0, a3y=0;
        const float4* Sv = (const float4*)Ssm + k_beg;
        #pragma unroll
        for (int k = 0; k < 16; k++) {
            float4 s4 = Sv[k];
            unsigned long long p;
            p = pk2(s4.x); a0x = fma2(p, w0[k], a0x); a0y = fma2(p, w1[k], a0y);
            p = pk2(s4.y); a1x = fma2(p, w0[k], a1x); a1y = fma2(p, w1[k], a1y);
            p = pk2(s4.z); a2x = fma2(p, w0[k], a2x); a2y = fma2(p, w1[k], a2y);
            p = pk2(s4.w); a3x = fma2(p, w0[k], a3x); a3y = fma2(p, w1[k], a3y);
        }
        {
            float* zrow = Zsm + kg * 256 + jq * 4;
            float2 lo, hi;
            lo = upk2(a0x); hi = upk2(a0y); *(float4*)(zrow +   0) = make_float4(lo.x, lo.y, hi.x, hi.y);
            lo = upk2(a1x); hi = upk2(a1y); *(float4*)(zrow +  64) = make_float4(lo.x, lo.y, hi.x, hi.y);
            lo = upk2(a2x); hi = upk2(a2y); *(float4*)(zrow + 128) = make_float4(lo.x, lo.y, hi.x, hi.y);
            lo = upk2(a3x); hi = upk2(a3y); *(float4*)(zrow + 192) = make_float4(lo.x, lo.y, hi.x, hi.y);
        }

        __syncthreads();

        // reduce 16 k-partials + input projection
        float z = zx;
        #pragma unroll
        for (int g = 0; g < 16; g++) z += Zsm[g * 256 + tid];

        // gather the 4 gates of one (b,u) via warp shuffle (lanes base..base+3)
        const int base = (tid & 31) & ~3;
        float zfv = __shfl_sync(0xFFFFFFFFu, z, base + 0);
        float ziv = __shfl_sync(0xFFFFFFFFu, z, base + 1);
        float zgv = __shfl_sync(0xFFFFFFFFu, z, base + 2);
        float zov = __shfl_sync(0xFFFFFFFFu, z, base + 3);

        if ((tid & 3) == 0) {
            float s_old = Ssm[(u0 + uu) * 4 + bb];
            float fg = sigm(zfv), ig = sigm(ziv), gd = sigm(zgv);
            float c  = ig * gd + fg * s_old;
            float o  = tanhf(zov);
            float ct = tanhf(c);
            float h  = o * ct;
            size_t oidx = ((size_t)(b0 + bb) * TN + t) * UN + (u0 + uu);
            out[oidx]         = h;
            out[c_off + oidx] = ct;
            __stcg(&g_S[nxt][b0 + bb][u0 + uu], ct);
        }
        __syncthreads();

        // team-local flag barrier: parallel release stores, parallel acquire polls
        if (tid == 0) st_rel(&g_flag[team][r][0], (unsigned)(t + 1));
        if (tid < 16) {
            while (ld_acq(&g_flag[team][tid][0]) < (unsigned)(t + 1)) { }
        }
        __syncthreads();
    }
}

// ---------------- launcher ---------------------------------------------------
extern "C" void kernel_launch(void* const* d_in, const int* in_sizes, int n_in,
                              void* d_out, int out_size) {
    const float* x  = (const float*)d_in[0];
    const float* h0 = (const float*)d_in[1];
    const float* Wf = (const float*)d_in[2];
    const float* Wi = (const float*)d_in[3];
    const float* Wc = (const float*)d_in[4];
    const float* Wo = (const float*)d_in[5];
    float* out = (float*)d_out;

    k_init<<<2048, 256>>>(Wf, Wi, Wc, Wo, h0);
    dim3 gg(NJ / 64, (TN * BN) / 64);   // (16, 2048)
    k_gemm<<<gg, 256>>>(x);
    k_rec<<<128, 256>>>(out);
}

// round 6
// speedup vs baseline: 1.2134x; 1.0294x over previous
#include <cuda_runtime.h>
#include <math.h>

#define BN 32
#define TN 4096
#define UN 256
#define NJ 1024
#define CL 8

// ---------------- static device scratch (no runtime allocation) -------------
__device__ float g_Zx[(size_t)TN * BN * NJ];   // [t*32+b][j] input projection
__device__ float g_Wp[512 * NJ];               // packed W: rows 0..255 s-part, 256..511 x-part; col j=g*256+u

// ---------------- helpers ----------------------------------------------------
__device__ __forceinline__ unsigned smem_u32(const void* p) {
    unsigned a;
    asm("{ .reg .u64 t; cvta.to.shared.u64 t, %1; cvt.u32.u64 %0, t; }"
        : "=r"(a) : "l"(p));
    return a;
}
__device__ __forceinline__ unsigned long long pk2(float v) {
    unsigned long long r; unsigned u = __float_as_uint(v);
    asm("mov.b64 %0, {%1, %1};" : "=l"(r) : "r"(u));
    return r;
}
__device__ __forceinline__ unsigned long long pack2(float lo, float hi) {
    unsigned long long r;
    asm("mov.b64 %0, {%1, %2};" : "=l"(r)
        : "r"(__float_as_uint(lo)), "r"(__float_as_uint(hi)));
    return r;
}
__device__ __forceinline__ unsigned long long fma2(unsigned long long a,
                                                   unsigned long long b,
                                                   unsigned long long c) {
    unsigned long long d;
    asm("fma.rn.f32x2 %0, %1, %2, %3;" : "=l"(d) : "l"(a), "l"(b), "l"(c));
    return d;
}
__device__ __forceinline__ float2 upk2(unsigned long long v) {
    unsigned lo, hi;
    asm("mov.b64 {%0, %1}, %2;" : "=r"(lo), "=r"(hi) : "l"(v));
    return make_float2(__uint_as_float(lo), __uint_as_float(hi));
}
__device__ __forceinline__ unsigned mapa_u32(unsigned local, unsigned rank) {
    unsigned r;
    asm("mapa.shared::cluster.u32 %0, %1, %2;" : "=r"(r) : "r"(local), "r"(rank));
    return r;
}
__device__ __forceinline__ void mbar_init(unsigned addr, unsigned cnt) {
    asm volatile("mbarrier.init.shared.b64 [%0], %1;" :: "r"(addr), "r"(cnt) : "memory");
}
__device__ __forceinline__ void mbar_arrive_cluster(unsigned addr) {
    asm volatile("mbarrier.arrive.shared::cluster.b64 _, [%0];" :: "r"(addr) : "memory");
}
__device__ __forceinline__ void mbar_wait_cluster(unsigned addr, unsigned parity) {
    asm volatile(
        "{\n\t"
        ".reg .pred P;\n\t"
        "WL_%=:\n\t"
        "mbarrier.try_wait.parity.acquire.cluster.shared::cta.b64 P, [%0], %1;\n\t"
        "@!P bra WL_%=;\n\t"
        "}"
        :: "r"(addr), "r"(parity) : "memory");
}
__device__ __forceinline__ void st_cluster_v4(unsigned addr, float4 v) {
    asm volatile("st.shared::cluster.v4.f32 [%0], {%1, %2, %3, %4};"
                 :: "r"(addr), "f"(v.x), "f"(v.y), "f"(v.z), "f"(v.w) : "memory");
}
__device__ __forceinline__ float sigm(float z) { return 1.0f / (1.0f + __expf(-z)); }

// ---------------- kernel: alignment rotator (so ncu -s 5 lands on k_rec) ----
__global__ void k_nop() {}

// ---------------- kernel 0: pack weights ------------------------------------
__global__ __launch_bounds__(256) void k_init(const float* __restrict__ Wf,
                                              const float* __restrict__ Wi,
                                              const float* __restrict__ Wc,
                                              const float* __restrict__ Wo) {
    int idx = blockIdx.x * blockDim.x + threadIdx.x;
    if (idx < 512 * 1024) {
        int k = idx >> 10, j = idx & 1023;
        int g = j >> 8,    u = j & 255;
        const float* W = (g == 0) ? Wf : (g == 1) ? Wi : (g == 2) ? Wc : Wo;
        g_Wp[idx] = W[k * 256 + u];
    }
}

// ---------------- kernel 1: input projection GEMM ---------------------------
__global__ __launch_bounds__(256) void k_gemm(const float* __restrict__ x) {
    __shared__ __align__(16) float As[16][64];
    __shared__ __align__(16) float Bs[16][64];

    const int tid = threadIdx.x;
    const int n0  = blockIdx.x * 64;
    const int m0  = blockIdx.y * 64;
    const int tm  = tid >> 4, tn = tid & 15;
    const int ar  = tid >> 2, akq = tid & 3;
    const int bkr = tid >> 4, bnq = tid & 15;

    const int m_glob = m0 + ar;
    const int bb = m_glob & 31, tt = m_glob >> 5;
    const float* arow = x + ((size_t)bb * TN + tt) * 256;

    unsigned long long a00=0, a01=0, a10=0, a11=0, a20=0, a21=0, a30=0, a31=0;

    float4 av = *(const float4*)(arow + akq * 4);
    float4 bv = *(const float4*)(g_Wp + (size_t)(256 + bkr) * NJ + n0 + bnq * 4);

    for (int k0 = 0; k0 < 256; k0 += 16) {
        __syncthreads();
        As[akq * 4 + 0][ar] = av.x;
        As[akq * 4 + 1][ar] = av.y;
        As[akq * 4 + 2][ar] = av.z;
        As[akq * 4 + 3][ar] = av.w;
        *(float4*)&Bs[bkr][bnq * 4] = bv;
        __syncthreads();

        if (k0 + 16 < 256) {
            av = *(const float4*)(arow + k0 + 16 + akq * 4);
            bv = *(const float4*)(g_Wp + (size_t)(256 + k0 + 16 + bkr) * NJ + n0 + bnq * 4);
        }
        #pragma unroll
        for (int kk = 0; kk < 16; kk++) {
            float4 a = *(const float4*)&As[kk][tm * 4];
            ulonglong2 w = *(const ulonglong2*)&Bs[kk][tn * 4];
            unsigned long long p;
            p = pk2(a.x); a00 = fma2(p, w.x, a00); a01 = fma2(p, w.y, a01);
            p = pk2(a.y); a10 = fma2(p, w.x, a10); a11 = fma2(p, w.y, a11);
            p = pk2(a.z); a20 = fma2(p, w.x, a20); a21 = fma2(p, w.y, a21);
            p = pk2(a.w); a30 = fma2(p, w.x, a30); a31 = fma2(p, w.y, a31);
        }
    }
    float2 lo, hi;
    lo = upk2(a00); hi = upk2(a01);
    *(float4*)(g_Zx + (size_t)(m0 + tm*4 + 0) * NJ + n0 + tn*4) = make_float4(lo.x, lo.y, hi.x, hi.y);
    lo = upk2(a10); hi = upk2(a11);
    *(float4*)(g_Zx + (size_t)(m0 + tm*4 + 1) * NJ + n0 + tn*4) = make_float4(lo.x, lo.y, hi.x, hi.y);
    lo = upk2(a20); hi = upk2(a21);
    *(float4*)(g_Zx + (size_t)(m0 + tm*4 + 2) * NJ + n0 + tn*4) = make_float4(lo.x, lo.y, hi.x, hi.y);
    lo = upk2(a30); hi = upk2(a31);
    *(float4*)(g_Zx + (size_t)(m0 + tm*4 + 3) * NJ + n0 + tn*4) = make_float4(lo.x, lo.y, hi.x, hi.y);
}

// ---------------- kernel 2: persistent recurrence (clusters + DSMEM) --------
// 16 clusters x 8 CTAs. Cluster c owns batches {2c, 2c+1}. CTA rank r owns
// u-range [r*32, r*32+32) -> 128 gate cols (jj = uu*4 + gate), weights in regs.
// State double-buffered in SMEM, exchanged via DSMEM stores + mbarrier.
__global__ __launch_bounds__(256, 1) __cluster_dims__(CL, 1, 1)
void k_rec(float* __restrict__ out, const float* __restrict__ h0) {
    __shared__ __align__(16) float Ssm[2][512];      // [parity][k*2 + b]
    __shared__ __align__(16) float Zsm[16][264];     // [kg][b*128 + jj], padded
    __shared__ __align__(16) float stg[64];          // [uu*2 + b]
    __shared__ __align__(8)  unsigned long long mbar[2];

    const int tid = threadIdx.x;
    unsigned r;
    asm("mov.u32 %0, %%cluster_ctarank;" : "=r"(r));
    const int team = blockIdx.x >> 3;
    const int b0   = team * 2;
    const int u0   = (int)r * 32;

    // matmul role
    const int kg = tid >> 4, jq = tid & 15, kbeg = kg * 16;
    // reduce/gate role (zi == tid)
    const int jj = tid & 127, bb = tid >> 7;
    const int gg = jj & 3,    uu = jj >> 2;
    const int jcol = gg * 256 + u0 + uu;
    const size_t c_off = (size_t)BN * TN * UN;

    const unsigned mb0 = smem_u32(&mbar[0]);
    const unsigned mb1 = smem_u32(&mbar[1]);
    if (tid == 0) { mbar_init(mb0, 8); mbar_init(mb1, 8); }

    // initial state for step 0 (local)
    Ssm[0][tid * 2 + 0] = h0[(b0 + 0) * 256 + tid];
    Ssm[0][tid * 2 + 1] = h0[(b0 + 1) * 256 + tid];

    // weight tile -> registers: 16 k x 8 cols (4 u64 pairs) per thread
    unsigned long long w[16][4];
    #pragma unroll
    for (int k = 0; k < 16; k++) {
        const float* row = g_Wp + (size_t)(kbeg + k) * NJ;
        #pragma unroll
        for (int jp = 0; jp < 4; jp++) {
            int j0 = jq * 8 + jp * 2;
            int cA = (j0 & 3) * 256 + u0 + (j0 >> 2);
            int cB = ((j0 + 1) & 3) * 256 + u0 + ((j0 + 1) >> 2);
            w[k][jp] = pack2(__ldg(row + cA), __ldg(row + cB));
        }
    }

    // pusher precompute: remote Ssm base + remote barrier addrs (rank = tid)
    unsigned dstA = 0, rbar0 = 0, rbar1 = 0;
    if (tid < 8) {
        dstA  = mapa_u32(smem_u32(&Ssm[0][u0 * 2]), (unsigned)tid);
        rbar0 = mapa_u32(mb0, (unsigned)tid);
        rbar1 = mapa_u32(mb1, (unsigned)tid);
    }

    __syncthreads();
    asm volatile("barrier.cluster.arrive.aligned;" ::: "memory");
    asm volatile("barrier.cluster.wait.aligned;" ::: "memory");

    for (int t = 0; t < TN; t++) {
        const int cur = t & 1;

        // prefetch input projection (independent of state)
        float zx = __ldcg(&g_Zx[((size_t)(t * 32 + b0 + bb)) * NJ + jcol]);

        // wait for exchange e = t-1 (barrier e&1, parity (e>>1)&1)
        if (t > 0) {
            const int e = t - 1;
            mbar_wait_cluster((e & 1) ? mb1 : mb0, (unsigned)((e >> 1) & 1));
        }

        // recurrent matmul: 16 k x 8 cols x 2 batches, weights in registers
        unsigned long long acc[2][4] = {{0,0,0,0},{0,0,0,0}};
        #pragma unroll
        for (int k = 0; k < 16; k++) {
            float2 s = *(const float2*)&Ssm[cur][(kbeg + k) * 2];
            unsigned long long p0 = pk2(s.x), p1 = pk2(s.y);
            #pragma unroll
            for (int jp = 0; jp < 4; jp++) {
                acc[0][jp] = fma2(p0, w[k][jp], acc[0][jp]);
                acc[1][jp] = fma2(p1, w[k][jp], acc[1][jp]);
            }
        }
        #pragma unroll
        for (int b = 0; b < 2; b++) {
            #pragma unroll
            for (int jp = 0; jp < 4; jp++) {
                float2 v = upk2(acc[b][jp]);
                *(float2*)&Zsm[kg][b * 128 + jq * 8 + jp * 2] = v;
            }
        }

        __syncthreads();

        // reduce 16 k-partials + input projection
        float z = zx;
        #pragma unroll
        for (int g = 0; g < 16; g++) z += Zsm[g][bb * 128 + jj];

        // gather 4 gates of one (b,u) via warp shuffle (consecutive lanes)
        const int base = (tid & 31) & ~3;
        float zf = __shfl_sync(0xFFFFFFFFu, z, base + 0);
        float zi = __shfl_sync(0xFFFFFFFFu, z, base + 1);
        float zg = __shfl_sync(0xFFFFFFFFu, z, base + 2);
        float zo = __shfl_sync(0xFFFFFFFFu, z, base + 3);

        if ((tid & 3) == 0) {
            float s_old = Ssm[cur][(u0 + uu) * 2 + bb];
            float f = sigm(zf), i = sigm(zi), g2 = sigm(zg);
            float c  = i * g2 + f * s_old;
            float ct = tanhf(c);
            float h  = tanhf(zo) * ct;
            size_t oidx = ((size_t)(b0 + bb) * TN + t) * UN + (u0 + uu);
            out[oidx]         = h;
            out[c_off + oidx] = ct;
            stg[uu * 2 + bb] = ct;
        }
        __syncthreads();

        // push new state to all 8 cluster CTAs' Ssm[(t+1)&1], then arrive
        if (t + 1 < TN && tid < 8) {
            unsigned dst = dstA + (unsigned)(((t + 1) & 1) * 2048);
            #pragma unroll
            for (int i2 = 0; i2 < 16; i2++) {
                float4 v = *(const float4*)&stg[i2 * 4];
                st_cluster_v4(dst + i2 * 16, v);
            }
            mbar_arrive_cluster((t & 1) ? rbar1 : rbar0);
        }
    }
}

// ---------------- launcher ---------------------------------------------------
extern "C" void kernel_launch(void* const* d_in, const int* in_sizes, int n_in,
                              void* d_out, int out_size) {
    const float* x  = (const float*)d_in[0];
    const float* h0 = (const float*)d_in[1];
    const float* Wf = (const float*)d_in[2];
    const float* Wi = (const float*)d_in[3];
    const float* Wc = (const float*)d_in[4];
    const float* Wo = (const float*)d_in[5];
    float* out = (float*)d_out;

    k_nop<<<1, 1>>>();
    k_init<<<2048, 256>>>(Wf, Wi, Wc, Wo);
    dim3 gg(NJ / 64, (TN * BN) / 64);   // (16, 2048)
    k_gemm<<<gg, 256>>>(x);
    k_rec<<<128, 256>>>(out, h0);
}